// round 1
// baseline (speedup 1.0000x reference)
#include <cuda_runtime.h>

// Problem constants
#define BB      8
#define HH      128
#define WW      128
#define DIM     512
#define NHEADS  8
#define HDIM    64
#define KW      7
#define RAD     3
#define M_TOTAL (BB * HH * WW)      // 131072
#define NTAPS   (KW * KW)            // 49

// Scratch: q (pre-scaled) and k, each [M_TOTAL, 512] fp32 (256 MB each).
// __device__ globals — allocation-guard safe.
__device__ float g_q[(size_t)M_TOTAL * DIM];
__device__ float g_k[(size_t)M_TOTAL * DIM];

// ---------------------------------------------------------------------------
// Kernel 1: qk = x @ W_qk   (M=131072, K=512, N=1024), fp32 SIMT tiled GEMM.
// 128x128 tile, BK=8, 256 threads, 8x8 microtile per thread (split-half
// layout: rows {ty*4+i, 64+ty*4+i}, cols {tx*4+j, 64+tx*4+j} for
// conflict-free float4 smem reads).
// Epilogue routes cols [0,512) -> g_q (scaled by 0.125), [512,1024) -> g_k.
// ---------------------------------------------------------------------------
__global__ __launch_bounds__(256, 2)
void gemm_qk_kernel(const float* __restrict__ A, const float* __restrict__ Bm)
{
    __shared__ float As[8][128];   // [k][m], transposed on store
    __shared__ float Bs[8][128];   // [k][n]

    const int tid = threadIdx.x;
    const int tx = tid & 15;       // 0..15
    const int ty = tid >> 4;       // 0..15
    const int m0 = blockIdx.y * 128;
    const int n0 = blockIdx.x * 128;

    float acc[8][8];
#pragma unroll
    for (int i = 0; i < 8; ++i)
#pragma unroll
        for (int j = 0; j < 8; ++j) acc[i][j] = 0.0f;

    // Per-thread load assignments
    const int ar = tid >> 1;              // 0..127 (A tile row)
    const int ac = (tid & 1) << 2;        // {0,4}  (A tile col, float4)
    const int br = tid >> 5;              // 0..7   (B tile row)
    const int bc = (tid & 31) << 2;       // 0..124 (B tile col, float4)

    const float* Aptr = A + (size_t)(m0 + ar) * DIM + ac;
    const float* Bptr = Bm + (size_t)br * 1024 + n0 + bc;

    for (int kk = 0; kk < DIM; kk += 8) {
        float4 av = *(const float4*)(Aptr + kk);
        float4 bv = *(const float4*)(Bptr + (size_t)kk * 1024);
        As[ac + 0][ar] = av.x;
        As[ac + 1][ar] = av.y;
        As[ac + 2][ar] = av.z;
        As[ac + 3][ar] = av.w;
        *(float4*)&Bs[br][bc] = bv;
        __syncthreads();

#pragma unroll
        for (int k = 0; k < 8; ++k) {
            float a[8], b[8];
            *(float4*)&a[0] = *(const float4*)&As[k][ty * 4];
            *(float4*)&a[4] = *(const float4*)&As[k][64 + ty * 4];
            *(float4*)&b[0] = *(const float4*)&Bs[k][tx * 4];
            *(float4*)&b[4] = *(const float4*)&Bs[k][64 + tx * 4];
#pragma unroll
            for (int i = 0; i < 8; ++i)
#pragma unroll
                for (int j = 0; j < 8; ++j)
                    acc[i][j] = fmaf(a[i], b[j], acc[i][j]);
        }
        __syncthreads();
    }

    const float scale = 0.125f;   // HEAD_DIM^-0.5
#pragma unroll
    for (int i = 0; i < 8; ++i) {
        const int m = m0 + ((i < 4) ? (ty * 4 + i) : (64 + ty * 4 + (i - 4)));
#pragma unroll
        for (int jh = 0; jh < 2; ++jh) {
            const int n = n0 + (jh ? (64 + tx * 4) : (tx * 4));
            float4 v;
            v.x = acc[i][jh * 4 + 0];
            v.y = acc[i][jh * 4 + 1];
            v.z = acc[i][jh * 4 + 2];
            v.w = acc[i][jh * 4 + 3];
            if (n < 512) {
                v.x *= scale; v.y *= scale; v.z *= scale; v.w *= scale;
                *(float4*)&g_q[(size_t)m * 512 + n] = v;
            } else {
                *(float4*)&g_k[(size_t)m * 512 + (n - 512)] = v;
            }
        }
    }
}

// ---------------------------------------------------------------------------
// Kernel 2: neighborhood attention logits.
// Block = one (b, head) and an 8x8 spatial pixel tile.
// smem: k halo tile (<=14x14 positions, 64 f32 each, stride 68 for
// conflict-free reads) + q tile (8x8x64). q cached in registers (16 float4).
// 4 threads per pixel, each covers taps {sub, sub+4, ...} of 49.
// out layout: (B, NHEADS, H, W, 49).
// ---------------------------------------------------------------------------
#define KSTRIDE 68                              // padded floats per k position
#define KSM_FLOATS (14 * 14 * KSTRIDE)          // 13328
#define QSM_FLOATS (64 * 64)                    // 4096
#define ATTN_SMEM_BYTES ((KSM_FLOATS + QSM_FLOATS) * 4)   // 69696... see below

__global__ __launch_bounds__(256, 2)
void neigh_attn_kernel(float* __restrict__ out)
{
    extern __shared__ float sm[];
    float* kS = sm;                    // [pos][KSTRIDE]
    float* qS = sm + KSM_FLOATS;       // [pixel][64]

    const int tid = threadIdx.x;
    const int bn  = blockIdx.z;        // b*8 + n
    const int r0  = blockIdx.y << 3;
    const int c0  = blockIdx.x << 3;
    const int b   = bn >> 3;
    const int n   = bn & 7;

    const int sr0 = max(r0 - RAD, 0);
    const int sr1 = min(r0 + 7 + RAD, HH - 1);   // covers clamped windows
    const int sc0 = max(c0 - RAD, 0);
    const int sc1 = min(c0 + 7 + RAD, WW - 1);
    const int nkr = sr1 - sr0 + 1;               // <= 14
    const int nkc = sc1 - sc0 + 1;               // <= 14
    const int npix = nkr * nkc;

    // Load k halo tile
    const float* kbase = g_k + (size_t)b * (HH * WW) * 512 + n * 64;
    for (int t = tid; t < npix * 16; t += 256) {
        const int pix = t >> 4;
        const int f   = t & 15;
        const int kr  = pix / nkc;
        const int kc  = pix - kr * nkc;
        float4 v = *(const float4*)(kbase +
                     ((size_t)(sr0 + kr) * WW + (sc0 + kc)) * 512 + f * 4);
        *(float4*)&kS[pix * KSTRIDE + f * 4] = v;
    }

    // Load q tile
    const float* qbase = g_q + (size_t)b * (HH * WW) * 512 + n * 64;
    for (int t = tid; t < 64 * 16; t += 256) {
        const int pix = t >> 4;
        const int f   = t & 15;
        const int pi  = pix >> 3;
        const int pj  = pix & 7;
        float4 v = *(const float4*)(qbase +
                     ((size_t)(r0 + pi) * WW + (c0 + pj)) * 512 + f * 4);
        *(float4*)&qS[pix * 64 + f * 4] = v;
    }
    __syncthreads();

    const int pixel = tid >> 2;        // 0..63
    const int sub   = tid & 3;         // 0..3
    const int pi = pixel >> 3;
    const int pj = pixel & 7;
    const int i = r0 + pi;
    const int j = c0 + pj;
    const int si = min(max(i - RAD, 0), HH - KW);   // clip to [0, 121]
    const int sj = min(max(j - RAD, 0), WW - KW);
    const int li = si - sr0;
    const int lj = sj - sc0;

    float4 qr[16];
#pragma unroll
    for (int f = 0; f < 16; ++f)
        qr[f] = *(const float4*)&qS[pixel * 64 + f * 4];

    float* obase = out + (((size_t)bn * HH + i) * WW + j) * NTAPS;

    for (int tap = sub; tap < NTAPS; tap += 4) {
        const int ki = tap / KW;
        const int kj = tap - ki * KW;
        const float* kp = &kS[((li + ki) * nkc + (lj + kj)) * KSTRIDE];
        float s = 0.0f;
#pragma unroll
        for (int f = 0; f < 16; ++f) {
            float4 kv = *(const float4*)&kp[f * 4];
            s = fmaf(qr[f].x, kv.x, s);
            s = fmaf(qr[f].y, kv.y, s);
            s = fmaf(qr[f].z, kv.z, s);
            s = fmaf(qr[f].w, kv.w, s);
        }
        obase[tap] = s;
    }
}

// ---------------------------------------------------------------------------
extern "C" void kernel_launch(void* const* d_in, const int* in_sizes, int n_in,
                              void* d_out, int out_size)
{
    const float* x = (const float*)d_in[0];     // (8,128,128,512) f32
    const float* w = (const float*)d_in[1];     // (512, 1024)     f32
    float* out = (float*)d_out;                 // (8,8,128,128,49) f32

    // GEMM: grid (N/128, M/128)
    gemm_qk_kernel<<<dim3(1024 / 128, M_TOTAL / 128), 256>>>(x, w);

    // Attention: opt in to >48KB dynamic smem (idempotent, capture-safe)
    cudaFuncSetAttribute(neigh_attn_kernel,
                         cudaFuncAttributeMaxDynamicSharedMemorySize,
                         ATTN_SMEM_BYTES);
    neigh_attn_kernel<<<dim3(WW / 8, HH / 8, BB * NHEADS), 256,
                        ATTN_SMEM_BYTES>>>(out);
}

// round 2
// speedup vs baseline: 1.9366x; 1.9366x over previous
#include <cuda_runtime.h>
#include <cstdint>

// Problem constants
#define BB      8
#define HH      128
#define WW      128
#define DIM     512
#define NHEADS  8
#define HDIM    64
#define KW      7
#define RAD     3
#define M_TOTAL (BB * HH * WW)      // 131072
#define NTAPS   (KW * KW)            // 49

// Scratch: q (pre-scaled) and k, each [M_TOTAL, 512] fp32.
__device__ float g_q[(size_t)M_TOTAL * DIM];
__device__ float g_k[(size_t)M_TOTAL * DIM];

// ---------------------------------------------------------------------------
// Kernel 1: qk = x @ W_qk via TF32 tensor-core MMA (m16n8k8).
// Block tile 128(M) x 128(N), BK=32, 256 threads = 8 warps in 4(M) x 2(N).
// Warp tile 32(M) x 64(N) = 2 m16 x 8 n8 MMA tiles. cp.async double-buffer.
// smem strides: As 36 (bank = lane, conflict-free), Bs 136 (8k+n distinct).
// ---------------------------------------------------------------------------
#define AS_STRIDE 36
#define BS_STRIDE 136
#define AS_BUF (128 * AS_STRIDE)   // 4608 floats
#define BS_BUF (32 * BS_STRIDE)    // 4352 floats
#define GEMM_SMEM ((2 * AS_BUF + 2 * BS_BUF) * 4)   // 71680 B

__device__ __forceinline__ uint32_t f2tf32(float f) {
    uint32_t u;
    asm("cvt.rna.tf32.f32 %0, %1;" : "=r"(u) : "f"(f));
    return u;
}

__device__ __forceinline__ void mma_tf32(float* c, const uint32_t* a, const uint32_t* b) {
    asm volatile(
        "mma.sync.aligned.m16n8k8.row.col.f32.tf32.tf32.f32 "
        "{%0,%1,%2,%3}, {%4,%5,%6,%7}, {%8,%9}, {%0,%1,%2,%3};\n"
        : "+f"(c[0]), "+f"(c[1]), "+f"(c[2]), "+f"(c[3])
        : "r"(a[0]), "r"(a[1]), "r"(a[2]), "r"(a[3]),
          "r"(b[0]), "r"(b[1]));
}

#define CP16(dst_u32, src_ptr) \
    asm volatile("cp.async.cg.shared.global [%0], [%1], 16;\n" :: "r"(dst_u32), "l"(src_ptr))
#define CP_COMMIT() asm volatile("cp.async.commit_group;\n")

__global__ __launch_bounds__(256, 2)
void gemm_qk_tf32_kernel(const float* __restrict__ A, const float* __restrict__ Bm)
{
    extern __shared__ float sm[];
    float* As = sm;                       // [2][128][AS_STRIDE]
    float* Bs = sm + 2 * AS_BUF;          // [2][32][BS_STRIDE]

    const int tid  = threadIdx.x;
    const int lane = tid & 31;
    const int wid  = tid >> 5;
    const int wm   = (wid & 3) * 32;      // warp M offset in tile
    const int wn   = (wid >> 2) * 64;     // warp N offset in tile
    const int m0   = blockIdx.y * 128;
    const int n0   = blockIdx.x * 128;

    float acc[2][8][4];
#pragma unroll
    for (int mt = 0; mt < 2; ++mt)
#pragma unroll
        for (int nt = 0; nt < 8; ++nt)
#pragma unroll
            for (int r = 0; r < 4; ++r) acc[mt][nt][r] = 0.0f;

    // --- async load assignments ---
    // A: thread t loads rows ar = t>>1, half h = t&1, 4 float4 along k.
    const int ar = tid >> 1;
    const int ah = (tid & 1) * 16;
    const float* Ag = A + (size_t)(m0 + ar) * DIM + ah;
    const uint32_t AsBase = (uint32_t)__cvta_generic_to_shared(As) +
                            (ar * AS_STRIDE + ah) * 4;
    // B: thread t loads k-row kb = t>>3, cols 4*((t&7) + 8i).
    const int bkr = tid >> 3;
    const int bc0 = (tid & 7) * 4;
    const float* Bg = Bm + (size_t)bkr * 1024 + n0 + bc0;
    const uint32_t BsBase = (uint32_t)__cvta_generic_to_shared(Bs) +
                            (bkr * BS_STRIDE + bc0) * 4;

    // fragment read offsets (element indices into buffer)
    const int a_row = wm + (lane >> 2);
    const int a_col = lane & 3;
    const int b_krow = lane & 3;
    const int b_col  = wn + (lane >> 2);

    // prologue: issue iter 0 into buffer 0
    {
#pragma unroll
        for (int i = 0; i < 4; ++i)
            CP16(AsBase + i * 16, Ag + i * 4);
#pragma unroll
        for (int i = 0; i < 4; ++i)
            CP16(BsBase + i * 32 * 4, Bg + i * 32);
        CP_COMMIT();
    }

    for (int it = 0; it < 16; ++it) {
        const int buf = it & 1;
        if (it + 1 < 16) {
            const int nb = (it + 1) & 1;
            const int kk = (it + 1) * 32;
#pragma unroll
            for (int i = 0; i < 4; ++i)
                CP16(AsBase + nb * AS_BUF * 4 + i * 16, Ag + kk + i * 4);
#pragma unroll
            for (int i = 0; i < 4; ++i)
                CP16(BsBase + nb * BS_BUF * 4 + i * 32 * 4,
                     Bg + (size_t)kk * 1024 + i * 32);
            CP_COMMIT();
            asm volatile("cp.async.wait_group 1;\n");
        } else {
            asm volatile("cp.async.wait_group 0;\n");
        }
        __syncthreads();

        const float* Ab = As + buf * AS_BUF;
        const float* Bb = Bs + buf * BS_BUF;

#pragma unroll
        for (int kb = 0; kb < 4; ++kb) {
            const int k0 = kb * 8;
            uint32_t afr[2][4];
#pragma unroll
            for (int mt = 0; mt < 2; ++mt) {
                const int r = a_row + mt * 16;
                const int c = k0 + a_col;
                afr[mt][0] = f2tf32(Ab[r * AS_STRIDE + c]);
                afr[mt][1] = f2tf32(Ab[(r + 8) * AS_STRIDE + c]);
                afr[mt][2] = f2tf32(Ab[r * AS_STRIDE + c + 4]);
                afr[mt][3] = f2tf32(Ab[(r + 8) * AS_STRIDE + c + 4]);
            }
            uint32_t bfr[8][2];
#pragma unroll
            for (int nt = 0; nt < 8; ++nt) {
                const int kr = k0 + b_krow;
                const int nc = b_col + nt * 8;
                bfr[nt][0] = f2tf32(Bb[kr * BS_STRIDE + nc]);
                bfr[nt][1] = f2tf32(Bb[(kr + 4) * BS_STRIDE + nc]);
            }
#pragma unroll
            for (int mt = 0; mt < 2; ++mt)
#pragma unroll
                for (int nt = 0; nt < 8; ++nt)
                    mma_tf32(acc[mt][nt], afr[mt], bfr[nt]);
        }
        __syncthreads();
    }

    // Epilogue: cols [0,512) -> q (scaled), [512,1024) -> k.
    const bool is_q = (n0 < 512);
    const float scale = 0.125f;
    float* dst = is_q ? g_q : g_k;
    const int ncol0 = is_q ? n0 : (n0 - 512);

#pragma unroll
    for (int mt = 0; mt < 2; ++mt) {
        const int r0 = m0 + wm + mt * 16 + (lane >> 2);
#pragma unroll
        for (int nt = 0; nt < 8; ++nt) {
            const int col = ncol0 + wn + nt * 8 + 2 * (lane & 3);
            float2 v0, v1;
            v0.x = acc[mt][nt][0]; v0.y = acc[mt][nt][1];
            v1.x = acc[mt][nt][2]; v1.y = acc[mt][nt][3];
            if (is_q) {
                v0.x *= scale; v0.y *= scale;
                v1.x *= scale; v1.y *= scale;
            }
            *(float2*)&dst[(size_t)r0 * 512 + col] = v0;
            *(float2*)&dst[(size_t)(r0 + 8) * 512 + col] = v1;
        }
    }
}

// ---------------------------------------------------------------------------
// Kernel 2: neighborhood attention logits (unchanged from round 1).
// ---------------------------------------------------------------------------
#define KSTRIDE 68
#define KSM_FLOATS (14 * 14 * KSTRIDE)
#define QSM_FLOATS (64 * 64)
#define ATTN_SMEM_BYTES ((KSM_FLOATS + QSM_FLOATS) * 4)

__global__ __launch_bounds__(256, 2)
void neigh_attn_kernel(float* __restrict__ out)
{
    extern __shared__ float sm[];
    float* kS = sm;
    float* qS = sm + KSM_FLOATS;

    const int tid = threadIdx.x;
    const int bn  = blockIdx.z;
    const int r0  = blockIdx.y << 3;
    const int c0  = blockIdx.x << 3;
    const int b   = bn >> 3;
    const int n   = bn & 7;

    const int sr0 = max(r0 - RAD, 0);
    const int sr1 = min(r0 + 7 + RAD, HH - 1);
    const int sc0 = max(c0 - RAD, 0);
    const int sc1 = min(c0 + 7 + RAD, WW - 1);
    const int nkr = sr1 - sr0 + 1;
    const int nkc = sc1 - sc0 + 1;
    const int npix = nkr * nkc;

    const float* kbase = g_k + (size_t)b * (HH * WW) * 512 + n * 64;
    for (int t = tid; t < npix * 16; t += 256) {
        const int pix = t >> 4;
        const int f   = t & 15;
        const int kr  = pix / nkc;
        const int kc  = pix - kr * nkc;
        float4 v = *(const float4*)(kbase +
                     ((size_t)(sr0 + kr) * WW + (sc0 + kc)) * 512 + f * 4);
        *(float4*)&kS[pix * KSTRIDE + f * 4] = v;
    }

    const float* qbase = g_q + (size_t)b * (HH * WW) * 512 + n * 64;
    for (int t = tid; t < 64 * 16; t += 256) {
        const int pix = t >> 4;
        const int f   = t & 15;
        const int pi  = pix >> 3;
        const int pj  = pix & 7;
        float4 v = *(const float4*)(qbase +
                     ((size_t)(r0 + pi) * WW + (c0 + pj)) * 512 + f * 4);
        *(float4*)&qS[pix * 64 + f * 4] = v;
    }
    __syncthreads();

    const int pixel = tid >> 2;
    const int sub   = tid & 3;
    const int pi = pixel >> 3;
    const int pj = pixel & 7;
    const int i = r0 + pi;
    const int j = c0 + pj;
    const int si = min(max(i - RAD, 0), HH - KW);
    const int sj = min(max(j - RAD, 0), WW - KW);
    const int li = si - sr0;
    const int lj = sj - sc0;

    float4 qr[16];
#pragma unroll
    for (int f = 0; f < 16; ++f)
        qr[f] = *(const float4*)&qS[pixel * 64 + f * 4];

    float* obase = out + (((size_t)bn * HH + i) * WW + j) * NTAPS;

    for (int tap = sub; tap < NTAPS; tap += 4) {
        const int ki = tap / KW;
        const int kj = tap - ki * KW;
        const float* kp = &kS[((li + ki) * nkc + (lj + kj)) * KSTRIDE];
        float s = 0.0f;
#pragma unroll
        for (int f = 0; f < 16; ++f) {
            float4 kv = *(const float4*)&kp[f * 4];
            s = fmaf(qr[f].x, kv.x, s);
            s = fmaf(qr[f].y, kv.y, s);
            s = fmaf(qr[f].z, kv.z, s);
            s = fmaf(qr[f].w, kv.w, s);
        }
        obase[tap] = s;
    }
}

// ---------------------------------------------------------------------------
extern "C" void kernel_launch(void* const* d_in, const int* in_sizes, int n_in,
                              void* d_out, int out_size)
{
    const float* x = (const float*)d_in[0];     // (8,128,128,512) f32
    const float* w = (const float*)d_in[1];     // (512, 1024)     f32
    float* out = (float*)d_out;                 // (8,8,128,128,49) f32

    cudaFuncSetAttribute(gemm_qk_tf32_kernel,
                         cudaFuncAttributeMaxDynamicSharedMemorySize,
                         GEMM_SMEM);
    gemm_qk_tf32_kernel<<<dim3(1024 / 128, M_TOTAL / 128), 256, GEMM_SMEM>>>(x, w);

    cudaFuncSetAttribute(neigh_attn_kernel,
                         cudaFuncAttributeMaxDynamicSharedMemorySize,
                         ATTN_SMEM_BYTES);
    neigh_attn_kernel<<<dim3(WW / 8, HH / 8, BB * NHEADS), 256,
                        ATTN_SMEM_BYTES>>>(out);
}

// round 3
// speedup vs baseline: 1.9431x; 1.0034x over previous
#include <cuda_runtime.h>
#include <cstdint>

// Problem constants
#define BB      8
#define HH      128
#define WW      128
#define DIM     512
#define NHEADS  8
#define HDIM    64
#define KW      7
#define RAD     3
#define M_TOTAL (BB * HH * WW)      // 131072
#define NTAPS   (KW * KW)            // 49

// Scratch: q (pre-scaled) and k, each [M_TOTAL, 512] fp32.
__device__ float g_q[(size_t)M_TOTAL * DIM];
__device__ float g_k[(size_t)M_TOTAL * DIM];

// ---------------------------------------------------------------------------
// Kernel 1: qk = x @ W_qk via TF32 tensor-core MMA (m16n8k8).
// Block tile 128(M) x 128(N), BK=32, 256 threads = 8 warps in 4(M) x 2(N).
// Warp tile 32(M) x 64(N) = 2 m16 x 8 n8 MMA tiles. cp.async double-buffer.
// smem strides: As 36 (bank = lane, conflict-free), Bs 136 (8k+n distinct).
// ---------------------------------------------------------------------------
#define AS_STRIDE 36
#define BS_STRIDE 136
#define AS_BUF (128 * AS_STRIDE)   // 4608 floats
#define BS_BUF (32 * BS_STRIDE)    // 4352 floats
#define GEMM_SMEM ((2 * AS_BUF + 2 * BS_BUF) * 4)   // 71680 B

__device__ __forceinline__ uint32_t f2tf32(float f) {
    uint32_t u;
    asm("cvt.rna.tf32.f32 %0, %1;" : "=r"(u) : "f"(f));
    return u;
}

__device__ __forceinline__ void mma_tf32(float* c, const uint32_t* a, const uint32_t* b) {
    asm volatile(
        "mma.sync.aligned.m16n8k8.row.col.f32.tf32.tf32.f32 "
        "{%0,%1,%2,%3}, {%4,%5,%6,%7}, {%8,%9}, {%0,%1,%2,%3};\n"
        : "+f"(c[0]), "+f"(c[1]), "+f"(c[2]), "+f"(c[3])
        : "r"(a[0]), "r"(a[1]), "r"(a[2]), "r"(a[3]),
          "r"(b[0]), "r"(b[1]));
}

#define CP16(dst_u32, src_ptr) \
    asm volatile("cp.async.cg.shared.global [%0], [%1], 16;\n" :: "r"(dst_u32), "l"(src_ptr))
#define CP_COMMIT() asm volatile("cp.async.commit_group;\n")

__global__ __launch_bounds__(256, 2)
void gemm_qk_tf32_kernel(const float* __restrict__ A, const float* __restrict__ Bm)
{
    extern __shared__ float sm[];
    float* As = sm;                       // [2][128][AS_STRIDE]
    float* Bs = sm + 2 * AS_BUF;          // [2][32][BS_STRIDE]

    const int tid  = threadIdx.x;
    const int lane = tid & 31;
    const int wid  = tid >> 5;
    const int wm   = (wid & 3) * 32;      // warp M offset in tile
    const int wn   = (wid >> 2) * 64;     // warp N offset in tile
    const int m0   = blockIdx.y * 128;
    const int n0   = blockIdx.x * 128;

    float acc[2][8][4];
#pragma unroll
    for (int mt = 0; mt < 2; ++mt)
#pragma unroll
        for (int nt = 0; nt < 8; ++nt)
#pragma unroll
            for (int r = 0; r < 4; ++r) acc[mt][nt][r] = 0.0f;

    // --- async load assignments ---
    // A: thread t loads rows ar = t>>1, half h = t&1, 4 float4 along k.
    const int ar = tid >> 1;
    const int ah = (tid & 1) * 16;
    const float* Ag = A + (size_t)(m0 + ar) * DIM + ah;
    const uint32_t AsBase = (uint32_t)__cvta_generic_to_shared(As) +
                            (ar * AS_STRIDE + ah) * 4;
    // B: thread t loads k-row kb = t>>3, cols 4*((t&7) + 8i).
    const int bkr = tid >> 3;
    const int bc0 = (tid & 7) * 4;
    const float* Bg = Bm + (size_t)bkr * 1024 + n0 + bc0;
    const uint32_t BsBase = (uint32_t)__cvta_generic_to_shared(Bs) +
                            (bkr * BS_STRIDE + bc0) * 4;

    // fragment read offsets (element indices into buffer)
    const int a_row = wm + (lane >> 2);
    const int a_col = lane & 3;
    const int b_krow = lane & 3;
    const int b_col  = wn + (lane >> 2);

    // prologue: issue iter 0 into buffer 0
    {
#pragma unroll
        for (int i = 0; i < 4; ++i)
            CP16(AsBase + i * 16, Ag + i * 4);
#pragma unroll
        for (int i = 0; i < 4; ++i)
            CP16(BsBase + i * 32 * 4, Bg + i * 32);
        CP_COMMIT();
    }

    for (int it = 0; it < 16; ++it) {
        const int buf = it & 1;
        if (it + 1 < 16) {
            const int nb = (it + 1) & 1;
            const int kk = (it + 1) * 32;
#pragma unroll
            for (int i = 0; i < 4; ++i)
                CP16(AsBase + nb * AS_BUF * 4 + i * 16, Ag + kk + i * 4);
#pragma unroll
            for (int i = 0; i < 4; ++i)
                CP16(BsBase + nb * BS_BUF * 4 + i * 32 * 4,
                     Bg + (size_t)kk * 1024 + i * 32);
            CP_COMMIT();
            asm volatile("cp.async.wait_group 1;\n");
        } else {
            asm volatile("cp.async.wait_group 0;\n");
        }
        __syncthreads();

        const float* Ab = As + buf * AS_BUF;
        const float* Bb = Bs + buf * BS_BUF;

#pragma unroll
        for (int kb = 0; kb < 4; ++kb) {
            const int k0 = kb * 8;
            uint32_t afr[2][4];
#pragma unroll
            for (int mt = 0; mt < 2; ++mt) {
                const int r = a_row + mt * 16;
                const int c = k0 + a_col;
                afr[mt][0] = f2tf32(Ab[r * AS_STRIDE + c]);
                afr[mt][1] = f2tf32(Ab[(r + 8) * AS_STRIDE + c]);
                afr[mt][2] = f2tf32(Ab[r * AS_STRIDE + c + 4]);
                afr[mt][3] = f2tf32(Ab[(r + 8) * AS_STRIDE + c + 4]);
            }
            uint32_t bfr[8][2];
#pragma unroll
            for (int nt = 0; nt < 8; ++nt) {
                const int kr = k0 + b_krow;
                const int nc = b_col + nt * 8;
                bfr[nt][0] = f2tf32(Bb[kr * BS_STRIDE + nc]);
                bfr[nt][1] = f2tf32(Bb[(kr + 4) * BS_STRIDE + nc]);
            }
#pragma unroll
            for (int mt = 0; mt < 2; ++mt)
#pragma unroll
                for (int nt = 0; nt < 8; ++nt)
                    mma_tf32(acc[mt][nt], afr[mt], bfr[nt]);
        }
        __syncthreads();
    }

    // Epilogue: cols [0,512) -> q (scaled), [512,1024) -> k.
    const bool is_q = (n0 < 512);
    const float scale = 0.125f;
    float* dst = is_q ? g_q : g_k;
    const int ncol0 = is_q ? n0 : (n0 - 512);

#pragma unroll
    for (int mt = 0; mt < 2; ++mt) {
        const int r0 = m0 + wm + mt * 16 + (lane >> 2);
#pragma unroll
        for (int nt = 0; nt < 8; ++nt) {
            const int col = ncol0 + wn + nt * 8 + 2 * (lane & 3);
            float2 v0, v1;
            v0.x = acc[mt][nt][0]; v0.y = acc[mt][nt][1];
            v1.x = acc[mt][nt][2]; v1.y = acc[mt][nt][3];
            if (is_q) {
                v0.x *= scale; v0.y *= scale;
                v1.x *= scale; v1.y *= scale;
            }
            *(float2*)&dst[(size_t)r0 * 512 + col] = v0;
            *(float2*)&dst[(size_t)(r0 + 8) * 512 + col] = v1;
        }
    }
}

// ---------------------------------------------------------------------------
// Kernel 2: neighborhood attention logits (unchanged from round 1).
// ---------------------------------------------------------------------------
#define KSTRIDE 68
#define KSM_FLOATS (14 * 14 * KSTRIDE)
#define QSM_FLOATS (64 * 64)
#define ATTN_SMEM_BYTES ((KSM_FLOATS + QSM_FLOATS) * 4)

__global__ __launch_bounds__(256, 2)
void neigh_attn_kernel(float* __restrict__ out)
{
    extern __shared__ float sm[];
    float* kS = sm;
    float* qS = sm + KSM_FLOATS;

    const int tid = threadIdx.x;
    const int bn  = blockIdx.z;
    const int r0  = blockIdx.y << 3;
    const int c0  = blockIdx.x << 3;
    const int b   = bn >> 3;
    const int n   = bn & 7;

    const int sr0 = max(r0 - RAD, 0);
    const int sr1 = min(r0 + 7 + RAD, HH - 1);
    const int sc0 = max(c0 - RAD, 0);
    const int sc1 = min(c0 + 7 + RAD, WW - 1);
    const int nkr = sr1 - sr0 + 1;
    const int nkc = sc1 - sc0 + 1;
    const int npix = nkr * nkc;

    const float* kbase = g_k + (size_t)b * (HH * WW) * 512 + n * 64;
    for (int t = tid; t < npix * 16; t += 256) {
        const int pix = t >> 4;
        const int f   = t & 15;
        const int kr  = pix / nkc;
        const int kc  = pix - kr * nkc;
        float4 v = *(const float4*)(kbase +
                     ((size_t)(sr0 + kr) * WW + (sc0 + kc)) * 512 + f * 4);
        *(float4*)&kS[pix * KSTRIDE + f * 4] = v;
    }

    const float* qbase = g_q + (size_t)b * (HH * WW) * 512 + n * 64;
    for (int t = tid; t < 64 * 16; t += 256) {
        const int pix = t >> 4;
        const int f   = t & 15;
        const int pi  = pix >> 3;
        const int pj  = pix & 7;
        float4 v = *(const float4*)(qbase +
                     ((size_t)(r0 + pi) * WW + (c0 + pj)) * 512 + f * 4);
        *(float4*)&qS[pix * 64 + f * 4] = v;
    }
    __syncthreads();

    const int pixel = tid >> 2;
    const int sub   = tid & 3;
    const int pi = pixel >> 3;
    const int pj = pixel & 7;
    const int i = r0 + pi;
    const int j = c0 + pj;
    const int si = min(max(i - RAD, 0), HH - KW);
    const int sj = min(max(j - RAD, 0), WW - KW);
    const int li = si - sr0;
    const int lj = sj - sc0;

    float4 qr[16];
#pragma unroll
    for (int f = 0; f < 16; ++f)
        qr[f] = *(const float4*)&qS[pixel * 64 + f * 4];

    float* obase = out + (((size_t)bn * HH + i) * WW + j) * NTAPS;

    for (int tap = sub; tap < NTAPS; tap += 4) {
        const int ki = tap / KW;
        const int kj = tap - ki * KW;
        const float* kp = &kS[((li + ki) * nkc + (lj + kj)) * KSTRIDE];
        float s = 0.0f;
#pragma unroll
        for (int f = 0; f < 16; ++f) {
            float4 kv = *(const float4*)&kp[f * 4];
            s = fmaf(qr[f].x, kv.x, s);
            s = fmaf(qr[f].y, kv.y, s);
            s = fmaf(qr[f].z, kv.z, s);
            s = fmaf(qr[f].w, kv.w, s);
        }
        obase[tap] = s;
    }
}

// ---------------------------------------------------------------------------
extern "C" void kernel_launch(void* const* d_in, const int* in_sizes, int n_in,
                              void* d_out, int out_size)
{
    const float* x = (const float*)d_in[0];     // (8,128,128,512) f32
    const float* w = (const float*)d_in[1];     // (512, 1024)     f32
    float* out = (float*)d_out;                 // (8,8,128,128,49) f32

    cudaFuncSetAttribute(gemm_qk_tf32_kernel,
                         cudaFuncAttributeMaxDynamicSharedMemorySize,
                         GEMM_SMEM);
    gemm_qk_tf32_kernel<<<dim3(1024 / 128, M_TOTAL / 128), 256, GEMM_SMEM>>>(x, w);

    cudaFuncSetAttribute(neigh_attn_kernel,
                         cudaFuncAttributeMaxDynamicSharedMemorySize,
                         ATTN_SMEM_BYTES);
    neigh_attn_kernel<<<dim3(WW / 8, HH / 8, BB * NHEADS), 256,
                        ATTN_SMEM_BYTES>>>(out);
}